// round 15
// baseline (speedup 1.0000x reference)
#include <cuda_runtime.h>
#include <cuda_fp16.h>

#define R     8192
#define D     64
#define TW    1000
#define TTOT  2000
#define NB    152     // one CTA per SM, full chip
#define NT    512     // 16 warps
#define WARPS 16
#define PINR  11      // rows pinned in SMEM per CTA (row 0 of warps 0..10)

// Row partition: CTA c<136 -> 54 rows at 54c ; c>=136 -> 53 rows at 7344+53(c-136)

// d_out layout (float32): prediction[1000,64], target[1000,64],
// prediction_augment[2000,64], target_augment[2000,64]
#define PRED_OFF 0
#define TGT_OFF  (1000*64)
#define PA_OFF   (2*1000*64)
#define TA_OFF   (4*1000*64)

// ---------------- device state ----------------
__device__ __half  d_Wh16[(size_t)R * R];   // 128 MB fp16 W_h (PERMUTED layout)
__device__ float   d_WoutT[(size_t)R * D];  // W_out transposed [r][i]
__device__ float   d_h[2][R];
__device__ float   d_osub[3][8][D];
__device__ unsigned d_bar_count;            // returns to 0 at every kernel exit
__device__ unsigned d_bar_gen;              // monotonic across replays (no reset)

// cache-policy creation (legal with .v4.u32 via L2::cache_hint)
__device__ __forceinline__ unsigned long long mkpol_keep() {
    unsigned long long p;
    asm("createpolicy.fractional.L2::evict_last.b64 %0, 1.0;" : "=l"(p));
    return p;
}
__device__ __forceinline__ unsigned long long mkpol_once() {
    unsigned long long p;
    asm("createpolicy.fractional.L2::evict_first.b64 %0, 1.0;" : "=l"(p));
    return p;
}
__device__ __forceinline__ uint4 ldg_pol(const uint4* p, unsigned long long pol) {
    uint4 v;
    asm("ld.global.nc.L2::cache_hint.v4.u32 {%0,%1,%2,%3}, [%4], %5;"
        : "=r"(v.x), "=r"(v.y), "=r"(v.z), "=r"(v.w) : "l"(p), "l"(pol));
    return v;
}

// ---------------- grid barrier (proven; gen is monotonic) ----------------
__device__ __forceinline__ void gridbar() {
    __threadfence();
    __syncthreads();
    if (threadIdx.x == 0) {
        volatile unsigned* vgen = (volatile unsigned*)&d_bar_gen;
        unsigned g = *vgen;
        unsigned a = atomicAdd(&d_bar_count, 1u);
        if (a == NB - 1) {
            *(volatile unsigned*)&d_bar_count = 0;
            __threadfence();
            *vgen = g + 1;
        } else {
            while (*vgen == g) { }
        }
        __threadfence();
    }
    __syncthreads();
}

__device__ __forceinline__ float dot8(uint4 q, float4 ha, float4 hb) {
    const __half2* h2 = reinterpret_cast<const __half2*>(&q);
    float2 f0 = __half22float2(h2[0]);
    float2 f1 = __half22float2(h2[1]);
    float2 f2 = __half22float2(h2[2]);
    float2 f3 = __half22float2(h2[3]);
    return f0.x * ha.x + f0.y * ha.y + f1.x * ha.z + f1.y * ha.w +
           f2.x * hb.x + f2.y * hb.y + f3.x * hb.z + f3.y * hb.w;
}

// dynamic smem layout (R11/R14)
#define SM_WC    0                               // PINR*16384 = 180224 B
#define SM_H     (PINR * R * 2)                  // 8192 floats = 32768 B
#define SM_ORED  (SM_H + R * 4)                  // 16*64 floats = 4096 B
#define SM_X     (SM_ORED + WARPS * 64 * 4)      // 64 floats = 256 B
#define SM_TOTAL (SM_X + 64 * 4)                 // 217600 B

// 4-row / 3-row bodies; L0..L3 are uint4 expressions using `idx`
#define MM4(L0, L1, L2, L3, SERP)                                  \
    _Pragma("unroll 4")                                            \
    for (int it = 0; it < 32; ++it) {                              \
        int itt = (SERP) ? (31 - it) : it;                         \
        int kb = itt * 256 + lane * 4;                             \
        int idx = itt * 32 + lane;                                 \
        float4 ha = *(const float4*)(h_sh + kb);                   \
        float4 hb = *(const float4*)(h_sh + kb + 128);             \
        uint4 q0 = L0; uint4 q1 = L1; uint4 q2 = L2; uint4 q3 = L3;\
        acc0 += dot8(q0, ha, hb);                                  \
        acc1 += dot8(q1, ha, hb);                                  \
        acc2 += dot8(q2, ha, hb);                                  \
        acc3 += dot8(q3, ha, hb);                                  \
    }

#define MM3(L0, L1, L2, SERP)                                      \
    _Pragma("unroll 4")                                            \
    for (int it = 0; it < 32; ++it) {                              \
        int itt = (SERP) ? (31 - it) : it;                         \
        int kb = itt * 256 + lane * 4;                             \
        int idx = itt * 32 + lane;                                 \
        float4 ha = *(const float4*)(h_sh + kb);                   \
        float4 hb = *(const float4*)(h_sh + kb + 128);             \
        uint4 q0 = L0; uint4 q1 = L1; uint4 q2 = L2;               \
        acc0 += dot8(q0, ha, hb);                                  \
        acc1 += dot8(q1, ha, hb);                                  \
        acc2 += dot8(q2, ha, hb);                                  \
    }

// ---------------- single persistent kernel: convert + prep + ESN ----------------
__global__ void __launch_bounds__(NT, 1)
k_esn(const float* __restrict__ xin,
      const float* __restrict__ Win,
      const float* __restrict__ Whf,
      const float* __restrict__ Wout,
      float* __restrict__ out) {
    extern __shared__ char smem[];
    __half* wc   = (__half*)(smem + SM_WC);
    float*  h_sh = (float*)(smem + SM_H);
    float*  ored = (float*)(smem + SM_ORED);
    float*  x_sh = (float*)(smem + SM_X);

    const int tid  = threadIdx.x;
    const int lane = tid & 31;
    const int warp = tid >> 5;
    const int cta  = blockIdx.x;
    const int gtid = cta * NT + tid;
    const int gstride = NB * NT;

    // ======== PROLOGUE PHASE A: fp32 -> fp16 weight convert (permuted) ========
    {
        size_t n = (size_t)R * R / 8;
        uint4* dst = (uint4*)d_Wh16;
        for (size_t o = (size_t)gtid; o < n; o += gstride) {
            size_t r = o >> 10;
            int rem = (int)(o & 1023);
            int it = rem >> 5, ln = rem & 31;
            const float* base = Whf + r * R + it * 256 + ln * 4;
            float4 a = *(const float4*)base;
            float4 b = *(const float4*)(base + 128);
            __half2 p0 = __floats2half2_rn(a.x, a.y);
            __half2 p1 = __floats2half2_rn(a.z, a.w);
            __half2 p2 = __floats2half2_rn(b.x, b.y);
            __half2 p3 = __floats2half2_rn(b.z, b.w);
            uint4 q;
            q.x = *reinterpret_cast<unsigned*>(&p0);
            q.y = *reinterpret_cast<unsigned*>(&p1);
            q.z = *reinterpret_cast<unsigned*>(&p2);
            q.w = *reinterpret_cast<unsigned*>(&p3);
            dst[o] = q;
        }
    }
    // ======== PROLOGUE PHASE B: transpose W_out, copy targets, init state ====
    for (int i = gtid; i < R * D; i += gstride) {
        int r = i / D, c = i % D;
        d_WoutT[i] = Wout[(size_t)c * R + r];
    }
    for (int i = gtid; i < TTOT * D; i += gstride) {
        float v = xin[i];
        out[TA_OFF + i] = v;
        if (i >= TW * D) out[TGT_OFF + i - TW * D] = v;
    }
    for (int i = gtid; i < R; i += gstride) { d_h[0][i] = 0.f; d_h[1][i] = 0.f; }
    if (gtid < 3 * 8 * D) ((float*)d_osub)[gtid] = 0.f;

    gridbar();   // all weights converted + state initialized, grid-wide

    const unsigned long long POL_KEEP = mkpol_keep();

    // ---- uneven row partition (identical to R14) ----
    const int nrows = (cta < 136) ? 54 : 53;
    const int rows0 = (cta < 136) ? 54 * cta : 7344 + 53 * (cta - 136);
    const int extra = nrows - 48;                       // # of 4-row warps (5 or 6)
    const int wr    = (warp < extra) ? 4 : 3;
    const int woff  = (warp < extra) ? 4 * warp : 4 * extra + 3 * (warp - extra);
    const int grow0 = rows0 + woff;

    // ---- pin row 0 of warps 0..10 in SMEM slot w ----
    {
        const unsigned long long POL_ONCE = mkpol_once();
        uint4* dst = (uint4*)wc;
        for (int i = tid; i < PINR * 1024; i += NT) {
            int slot = i >> 10;
            int off  = i & 1023;
            int wo = (slot < extra) ? 4 * slot : 4 * extra + 3 * (slot - extra);
            const uint4* src = (const uint4*)d_Wh16 + (size_t)(rows0 + wo) * 1024;
            dst[i] = ldg_pol(src + off, POL_ONCE);
        }
    }

    const uint4* g0 = (const uint4*)(d_Wh16 + (size_t)(grow0 + 0) * R);
    const uint4* g1 = (const uint4*)(d_Wh16 + (size_t)(grow0 + 1) * R);
    const uint4* g2 = (const uint4*)(d_Wh16 + (size_t)(grow0 + 2) * R);
    const uint4* g3 = (const uint4*)(d_Wh16 + (size_t)(grow0 + 3) * R);
    const uint4* c0 = (const uint4*)(wc + (size_t)warp * R);   // own pinned row 0
    const float* winr = Win + (size_t)grow0 * D + 2 * lane;
    const float* wt   = d_WoutT + (size_t)grow0 * D;
    __syncthreads();

    for (int s = 0; s < TTOT; ++s) {
        const bool rev = (s & 1);
        // ---- publish out(h_s), prepare x, recycle buffers ----
        if (tid < D) {
            float o = 0.f;
            if (cta == 0 || s >= TW) {
                #pragma unroll
                for (int b = 0; b < 8; ++b) o += d_osub[s % 3][b][tid];
            }
            if (cta == 0) {
                if (s >= 1 && s <= TW) out[PA_OFF + (s - 1) * D + tid] = o;
                if (s >= TW) {
                    out[PRED_OFF + (s - TW) * D + tid] = o;
                    out[PA_OFF + s * D + tid] = o;
                }
            }
            if (cta < 8) d_osub[(s + 2) % 3][cta][tid] = 0.f;
            x_sh[tid] = (s < TW) ? xin[(size_t)s * D + tid] : o;
        }
        // ---- stage h_s into shared (fp32, plain loads) ----
        {
            const float4* hsrc = (const float4*)d_h[s & 1];
            for (int i = tid; i < R / 4; i += NT) ((float4*)h_sh)[i] = hsrc[i];
        }
        __syncthreads();

        // ---- W_h @ h : row 0 pinned for warps 0-10; all streamed rows serpentine ----
        float acc0 = 0.f, acc1 = 0.f, acc2 = 0.f, acc3 = 0.f;
        if (warp < PINR) {
            if (wr == 4) {
                MM4(c0[idx], ldg_pol(g1 + idx, POL_KEEP),
                    ldg_pol(g2 + idx, POL_KEEP), ldg_pol(g3 + idx, POL_KEEP), rev)
            } else {
                MM3(c0[idx], ldg_pol(g1 + idx, POL_KEEP),
                    ldg_pol(g2 + idx, POL_KEEP), rev)
            }
        } else {   // warps 11-15 always have wr == 3
            MM3(ldg_pol(g0 + idx, POL_KEEP), ldg_pol(g1 + idx, POL_KEEP),
                ldg_pol(g2 + idx, POL_KEEP), rev)
        }

        // ---- + W_in @ x ----
        {
            float xa = x_sh[2 * lane], xb = x_sh[2 * lane + 1];
            acc0 += winr[0]         * xa + winr[1]         * xb;
            acc1 += winr[D]         * xa + winr[D + 1]     * xb;
            acc2 += winr[2 * D]     * xa + winr[2 * D + 1] * xb;
            if (wr == 4)
                acc3 += winr[3 * D] * xa + winr[3 * D + 1] * xb;
        }
        #pragma unroll
        for (int o = 16; o; o >>= 1) {
            acc0 += __shfl_xor_sync(0xffffffffu, acc0, o);
            acc1 += __shfl_xor_sync(0xffffffffu, acc1, o);
            acc2 += __shfl_xor_sync(0xffffffffu, acc2, o);
            acc3 += __shfl_xor_sync(0xffffffffu, acc3, o);
        }
        // ---- lane-parallel tanh + h store + aug ----
        float pre = (lane == 0) ? acc0 : (lane == 1) ? acc1
                  : (lane == 2) ? acc2 : acc3;
        float hv = tanhf(pre);
        float av = 0.f;
        if (lane < wr) {
            d_h[(s + 1) & 1][grow0 + lane] = hv;
            av = (((grow0 + lane) & 1) == 0) ? hv * hv : hv;
        }
        float a0 = __shfl_sync(0xffffffffu, av, 0);
        float a1 = __shfl_sync(0xffffffffu, av, 1);
        float a2 = __shfl_sync(0xffffffffu, av, 2);
        float a3 = __shfl_sync(0xffffffffu, av, 3);

        // ---- fused readout partials: W_out @ aug(h_{s+1}) ----
        float p0 = wt[lane]      * a0 + wt[D + lane]      * a1 + wt[2 * D + lane]      * a2;
        float p1 = wt[32 + lane] * a0 + wt[D + 32 + lane] * a1 + wt[2 * D + 32 + lane] * a2;
        if (wr == 4) {
            p0 += wt[3 * D + lane]      * a3;
            p1 += wt[3 * D + 32 + lane] * a3;
        }
        ored[warp * 64 + lane]      = p0;
        ored[warp * 64 + 32 + lane] = p1;
        __syncthreads();
        if (tid < D) {
            float sum = 0.f;
            #pragma unroll
            for (int w = 0; w < WARPS; ++w) sum += ored[w * 64 + tid];
            atomicAdd(&d_osub[(s + 1) % 3][cta & 7][tid], sum);
        }
        gridbar();
    }
}

// ---------------- launch: ONE kernel, so ncu must capture k_esn ----------------
extern "C" void kernel_launch(void* const* d_in, const int* in_sizes, int n_in,
                              void* d_out, int out_size) {
    const float* xin  = (const float*)d_in[0];
    const float* Win  = (const float*)d_in[1];
    const float* Whf  = (const float*)d_in[2];
    const float* Wout = (const float*)d_in[3];
    float* out = (float*)d_out;

    static bool attr_set = false;
    if (!attr_set) {
        cudaFuncSetAttribute(k_esn, cudaFuncAttributeMaxDynamicSharedMemorySize, SM_TOTAL);
        attr_set = true;
    }

    k_esn<<<NB, NT, SM_TOTAL>>>(xin, Win, Whf, Wout, out);
}

// round 16
// speedup vs baseline: 1.0476x; 1.0476x over previous
#include <cuda_runtime.h>
#include <cuda_fp16.h>

#define R     8192
#define D     64
#define TW    1000
#define TTOT  2000
#define NB    152     // one CTA per SM, full chip
#define NT    512     // 16 warps
#define WARPS 16
#define PINR  11      // rows pinned in SMEM per CTA (row 0 of warps 0..10)

// Row partition: CTA c<136 -> 54 rows at 54c ; c>=136 -> 53 rows at 7344+53(c-136)

// d_out layout (float32): prediction[1000,64], target[1000,64],
// prediction_augment[2000,64], target_augment[2000,64]
#define PRED_OFF 0
#define TGT_OFF  (1000*64)
#define PA_OFF   (2*1000*64)
#define TA_OFF   (4*1000*64)

// ---------------- device state ----------------
__device__ __half  d_Wh16[(size_t)R * R];   // 128 MB fp16 W_h (PERMUTED layout)
__device__ float   d_WoutT[(size_t)R * D];  // W_out transposed [r][i]
__device__ float   d_h[2][R];
__device__ float   d_osub[3][8][D];
__device__ unsigned d_bar_count;
__device__ unsigned d_bar_gen;

// cache-policy creation
__device__ __forceinline__ unsigned long long mkpol_keep() {
    unsigned long long p;
    asm("createpolicy.fractional.L2::evict_last.b64 %0, 1.0;" : "=l"(p));
    return p;
}
__device__ __forceinline__ unsigned long long mkpol_once() {
    unsigned long long p;
    asm("createpolicy.fractional.L2::evict_first.b64 %0, 1.0;" : "=l"(p));
    return p;
}
// streamed-weight load: L1 BYPASS (.cg — only ~10KB L1 left after smem carveout,
// allocation there is pure thrash on the busiest pipe) + L2 evict_last protect.
__device__ __forceinline__ uint4 ldg_pol(const uint4* p, unsigned long long pol) {
    uint4 v;
    asm("ld.global.cg.L2::cache_hint.v4.u32 {%0,%1,%2,%3}, [%4], %5;"
        : "=r"(v.x), "=r"(v.y), "=r"(v.z), "=r"(v.w) : "l"(p), "l"(pol));
    return v;
}

// ---------------- prologue: fp32 -> fp16, permuted for conflict-free LDS ----
// uint4 (r, it, lane) holds src k = it*256 + lane*4 + {0..3} in halves 0-3
// and src k = it*256 + 128 + lane*4 + {0..3} in halves 4-7.
__global__ void k_convert(const float* __restrict__ Wh) {
    size_t n = (size_t)R * R / 8;
    uint4* dst = (uint4*)d_Wh16;
    for (size_t o = (size_t)blockIdx.x * blockDim.x + threadIdx.x; o < n;
         o += (size_t)gridDim.x * blockDim.x) {
        size_t r = o >> 10;
        int rem = (int)(o & 1023);
        int it = rem >> 5, lane = rem & 31;
        const float* base = Wh + r * R + it * 256 + lane * 4;
        float4 a = *(const float4*)base;
        float4 b = *(const float4*)(base + 128);
        __half2 p0 = __floats2half2_rn(a.x, a.y);
        __half2 p1 = __floats2half2_rn(a.z, a.w);
        __half2 p2 = __floats2half2_rn(b.x, b.y);
        __half2 p3 = __floats2half2_rn(b.z, b.w);
        uint4 q;
        q.x = *reinterpret_cast<unsigned*>(&p0);
        q.y = *reinterpret_cast<unsigned*>(&p1);
        q.z = *reinterpret_cast<unsigned*>(&p2);
        q.w = *reinterpret_cast<unsigned*>(&p3);
        dst[o] = q;
    }
}

// ---------------- prologue ----------------
__global__ void k_prep(const float* __restrict__ Wout,
                       const float* __restrict__ xin,
                       float* __restrict__ out) {
    int tid = blockIdx.x * blockDim.x + threadIdx.x;
    int stride = gridDim.x * blockDim.x;
    for (int i = tid; i < R * D; i += stride) {
        int r = i / D, c = i % D;
        d_WoutT[i] = Wout[(size_t)c * R + r];
    }
    for (int i = tid; i < TTOT * D; i += stride) {
        float v = xin[i];
        out[TA_OFF + i] = v;
        if (i >= TW * D) out[TGT_OFF + i - TW * D] = v;
    }
    for (int i = tid; i < R; i += stride) { d_h[0][i] = 0.f; d_h[1][i] = 0.f; }
    if (tid < 3 * 8 * D) ((float*)d_osub)[tid] = 0.f;
    if (tid == 0) { d_bar_count = 0; d_bar_gen = 0; }
}

// ---------------- grid barrier (proven) ----------------
__device__ __forceinline__ void gridbar() {
    __threadfence();
    __syncthreads();
    if (threadIdx.x == 0) {
        volatile unsigned* vgen = (volatile unsigned*)&d_bar_gen;
        unsigned g = *vgen;
        unsigned a = atomicAdd(&d_bar_count, 1u);
        if (a == NB - 1) {
            *(volatile unsigned*)&d_bar_count = 0;
            __threadfence();
            *vgen = g + 1;
        } else {
            while (*vgen == g) { }
        }
        __threadfence();
    }
    __syncthreads();
}

__device__ __forceinline__ float dot8(uint4 q, float4 ha, float4 hb) {
    const __half2* h2 = reinterpret_cast<const __half2*>(&q);
    float2 f0 = __half22float2(h2[0]);
    float2 f1 = __half22float2(h2[1]);
    float2 f2 = __half22float2(h2[2]);
    float2 f3 = __half22float2(h2[3]);
    return f0.x * ha.x + f0.y * ha.y + f1.x * ha.z + f1.y * ha.w +
           f2.x * hb.x + f2.y * hb.y + f3.x * hb.z + f3.y * hb.w;
}

// dynamic smem layout (R11/R14)
#define SM_WC    0                               // PINR*16384 = 180224 B
#define SM_H     (PINR * R * 2)                  // 8192 floats = 32768 B
#define SM_ORED  (SM_H + R * 4)                  // 16*64 floats = 4096 B
#define SM_X     (SM_ORED + WARPS * 64 * 4)      // 64 floats = 256 B
#define SM_TOTAL (SM_X + 64 * 4)                 // 217600 B

// 4-row / 3-row bodies; L0..L3 are uint4 expressions using `idx`
#define MM4(L0, L1, L2, L3, SERP)                                  \
    _Pragma("unroll 4")                                            \
    for (int it = 0; it < 32; ++it) {                              \
        int itt = (SERP) ? (31 - it) : it;                         \
        int kb = itt * 256 + lane * 4;                             \
        int idx = itt * 32 + lane;                                 \
        float4 ha = *(const float4*)(h_sh + kb);                   \
        float4 hb = *(const float4*)(h_sh + kb + 128);             \
        uint4 q0 = L0; uint4 q1 = L1; uint4 q2 = L2; uint4 q3 = L3;\
        acc0 += dot8(q0, ha, hb);                                  \
        acc1 += dot8(q1, ha, hb);                                  \
        acc2 += dot8(q2, ha, hb);                                  \
        acc3 += dot8(q3, ha, hb);                                  \
    }

#define MM3(L0, L1, L2, SERP)                                      \
    _Pragma("unroll 4")                                            \
    for (int it = 0; it < 32; ++it) {                              \
        int itt = (SERP) ? (31 - it) : it;                         \
        int kb = itt * 256 + lane * 4;                             \
        int idx = itt * 32 + lane;                                 \
        float4 ha = *(const float4*)(h_sh + kb);                   \
        float4 hb = *(const float4*)(h_sh + kb + 128);             \
        uint4 q0 = L0; uint4 q1 = L1; uint4 q2 = L2;               \
        acc0 += dot8(q0, ha, hb);                                  \
        acc1 += dot8(q1, ha, hb);                                  \
        acc2 += dot8(q2, ha, hb);                                  \
    }

// ---------------- persistent ESN kernel ----------------
__global__ void __launch_bounds__(NT, 1)
k_esn(const float* __restrict__ xin,
      const float* __restrict__ Win,
      float* __restrict__ out) {
    extern __shared__ char smem[];
    __half* wc   = (__half*)(smem + SM_WC);
    float*  h_sh = (float*)(smem + SM_H);
    float*  ored = (float*)(smem + SM_ORED);
    float*  x_sh = (float*)(smem + SM_X);

    const int tid  = threadIdx.x;
    const int lane = tid & 31;
    const int warp = tid >> 5;
    const int cta  = blockIdx.x;

    const unsigned long long POL_KEEP = mkpol_keep();

    // ---- uneven row partition (identical to R14) ----
    const int nrows = (cta < 136) ? 54 : 53;
    const int rows0 = (cta < 136) ? 54 * cta : 7344 + 53 * (cta - 136);
    const int extra = nrows - 48;                       // # of 4-row warps (5 or 6)
    const int wr    = (warp < extra) ? 4 : 3;
    const int woff  = (warp < extra) ? 4 * warp : 4 * extra + 3 * (warp - extra);
    const int grow0 = rows0 + woff;

    // ---- pin row 0 of warps 0..10 in SMEM slot w (spread the LDS work) ----
    {
        const unsigned long long POL_ONCE = mkpol_once();
        uint4* dst = (uint4*)wc;
        for (int i = tid; i < PINR * 1024; i += NT) {
            int slot = i >> 10;            // which pinned warp's row
            int off  = i & 1023;
            int wo = (slot < extra) ? 4 * slot : 4 * extra + 3 * (slot - extra);
            const uint4* src = (const uint4*)d_Wh16 + (size_t)(rows0 + wo) * 1024;
            dst[i] = ldg_pol(src + off, POL_ONCE);
        }
    }

    const uint4* g0 = (const uint4*)(d_Wh16 + (size_t)(grow0 + 0) * R);
    const uint4* g1 = (const uint4*)(d_Wh16 + (size_t)(grow0 + 1) * R);
    const uint4* g2 = (const uint4*)(d_Wh16 + (size_t)(grow0 + 2) * R);
    const uint4* g3 = (const uint4*)(d_Wh16 + (size_t)(grow0 + 3) * R);
    const uint4* c0 = (const uint4*)(wc + (size_t)warp * R);   // own pinned row 0
    const float* winr = Win + (size_t)grow0 * D + 2 * lane;
    const float* wt   = d_WoutT + (size_t)grow0 * D;
    __syncthreads();

    for (int s = 0; s < TTOT; ++s) {
        const bool rev = (s & 1);
        // ---- publish out(h_s), prepare x, recycle buffers ----
        if (tid < D) {
            float o = 0.f;
            if (cta == 0 || s >= TW) {
                #pragma unroll
                for (int b = 0; b < 8; ++b) o += d_osub[s % 3][b][tid];
            }
            if (cta == 0) {
                if (s >= 1 && s <= TW) out[PA_OFF + (s - 1) * D + tid] = o;
                if (s >= TW) {
                    out[PRED_OFF + (s - TW) * D + tid] = o;
                    out[PA_OFF + s * D + tid] = o;
                }
            }
            if (cta < 8) d_osub[(s + 2) % 3][cta][tid] = 0.f;
            x_sh[tid] = (s < TW) ? xin[(size_t)s * D + tid] : o;
        }
        // ---- stage h_s into shared (fp32, plain loads) ----
        {
            const float4* hsrc = (const float4*)d_h[s & 1];
            for (int i = tid; i < R / 4; i += NT) ((float4*)h_sh)[i] = hsrc[i];
        }
        __syncthreads();

        // ---- W_h @ h : row 0 pinned for warps 0-10; streamed rows serpentine, .cg ----
        float acc0 = 0.f, acc1 = 0.f, acc2 = 0.f, acc3 = 0.f;
        if (warp < PINR) {
            if (wr == 4) {
                MM4(c0[idx], ldg_pol(g1 + idx, POL_KEEP),
                    ldg_pol(g2 + idx, POL_KEEP), ldg_pol(g3 + idx, POL_KEEP), rev)
            } else {
                MM3(c0[idx], ldg_pol(g1 + idx, POL_KEEP),
                    ldg_pol(g2 + idx, POL_KEEP), rev)
            }
        } else {   // warps 11-15 always have wr == 3
            MM3(ldg_pol(g0 + idx, POL_KEEP), ldg_pol(g1 + idx, POL_KEEP),
                ldg_pol(g2 + idx, POL_KEEP), rev)
        }

        // ---- + W_in @ x ----
        {
            float xa = x_sh[2 * lane], xb = x_sh[2 * lane + 1];
            acc0 += winr[0]         * xa + winr[1]         * xb;
            acc1 += winr[D]         * xa + winr[D + 1]     * xb;
            acc2 += winr[2 * D]     * xa + winr[2 * D + 1] * xb;
            if (wr == 4)
                acc3 += winr[3 * D] * xa + winr[3 * D + 1] * xb;
        }
        #pragma unroll
        for (int o = 16; o; o >>= 1) {
            acc0 += __shfl_xor_sync(0xffffffffu, acc0, o);
            acc1 += __shfl_xor_sync(0xffffffffu, acc1, o);
            acc2 += __shfl_xor_sync(0xffffffffu, acc2, o);
            acc3 += __shfl_xor_sync(0xffffffffu, acc3, o);
        }
        // ---- lane-parallel tanh + h store + aug ----
        float pre = (lane == 0) ? acc0 : (lane == 1) ? acc1
                  : (lane == 2) ? acc2 : acc3;
        float hv = tanhf(pre);
        float av = 0.f;
        if (lane < wr) {
            d_h[(s + 1) & 1][grow0 + lane] = hv;
            av = (((grow0 + lane) & 1) == 0) ? hv * hv : hv;
        }
        float a0 = __shfl_sync(0xffffffffu, av, 0);
        float a1 = __shfl_sync(0xffffffffu, av, 1);
        float a2 = __shfl_sync(0xffffffffu, av, 2);
        float a3 = __shfl_sync(0xffffffffu, av, 3);

        // ---- fused readout partials: W_out @ aug(h_{s+1}) ----
        float p0 = wt[lane]      * a0 + wt[D + lane]      * a1 + wt[2 * D + lane]      * a2;
        float p1 = wt[32 + lane] * a0 + wt[D + 32 + lane] * a1 + wt[2 * D + 32 + lane] * a2;
        if (wr == 4) {
            p0 += wt[3 * D + lane]      * a3;
            p1 += wt[3 * D + 32 + lane] * a3;
        }
        ored[warp * 64 + lane]      = p0;
        ored[warp * 64 + 32 + lane] = p1;
        __syncthreads();
        if (tid < D) {
            float sum = 0.f;
            #pragma unroll
            for (int w = 0; w < WARPS; ++w) sum += ored[w * 64 + tid];
            atomicAdd(&d_osub[(s + 1) % 3][cta & 7][tid], sum);
        }
        gridbar();
    }
}

// ---------------- launch ----------------
extern "C" void kernel_launch(void* const* d_in, const int* in_sizes, int n_in,
                              void* d_out, int out_size) {
    const float* xin  = (const float*)d_in[0];
    const float* Win  = (const float*)d_in[1];
    const float* Whf  = (const float*)d_in[2];
    const float* Wout = (const float*)d_in[3];
    float* out = (float*)d_out;

    static bool attr_set = false;
    if (!attr_set) {
        cudaFuncSetAttribute(k_esn, cudaFuncAttributeMaxDynamicSharedMemorySize, SM_TOTAL);
        attr_set = true;
    }

    k_convert<<<4096, 256>>>(Whf);
    k_prep<<<1024, 256>>>(Wout, xin, out);
    k_esn<<<NB, NT, SM_TOTAL>>>(xin, Win, out);
}

// round 17
// speedup vs baseline: 1.0682x; 1.0196x over previous
#include <cuda_runtime.h>
#include <cuda_fp16.h>

#define R     8192
#define D     64
#define TW    1000
#define TTOT  2000
#define NB    152     // one CTA per SM, full chip
#define NT    512     // 16 warps
#define WARPS 16
#define PINR  11      // rows pinned in SMEM per CTA (row 0 of warps 0..10)

// Row partition: CTA c<136 -> 54 rows at 54c ; c>=136 -> 53 rows at 7344+53(c-136)

// d_out layout (float32): prediction[1000,64], target[1000,64],
// prediction_augment[2000,64], target_augment[2000,64]
#define PRED_OFF 0
#define TGT_OFF  (1000*64)
#define PA_OFF   (2*1000*64)
#define TA_OFF   (4*1000*64)

// ---------------- device state ----------------
__device__ __half  d_Wh16[(size_t)R * R];   // 128 MB fp16 W_h (PERMUTED layout)
__device__ float   d_WoutT[(size_t)R * D];  // W_out transposed [r][i]
__device__ float   d_h[2][R];
__device__ float   d_osub[3][8][D];
__device__ unsigned d_bar_count;
__device__ unsigned d_bar_gen;

// cache-policy creation
__device__ __forceinline__ unsigned long long mkpol_keep() {
    unsigned long long p;
    asm("createpolicy.fractional.L2::evict_last.b64 %0, 1.0;" : "=l"(p));
    return p;
}
__device__ __forceinline__ unsigned long long mkpol_once() {
    unsigned long long p;
    asm("createpolicy.fractional.L2::evict_first.b64 %0, 1.0;" : "=l"(p));
    return p;
}
// streamed-weight load: L1 bypass (.cg) + L2 evict_last protect (proven R11+R16)
__device__ __forceinline__ uint4 ldg_pol(const uint4* p, unsigned long long pol) {
    uint4 v;
    asm("ld.global.cg.L2::cache_hint.v4.u32 {%0,%1,%2,%3}, [%4], %5;"
        : "=r"(v.x), "=r"(v.y), "=r"(v.z), "=r"(v.w) : "l"(p), "l"(pol));
    return v;
}

// ---- fence-free barrier primitives (CG grid.sync pattern) ----
__device__ __forceinline__ unsigned ld_acquire_gpu(unsigned* p) {
    unsigned v;
    asm volatile("ld.acquire.gpu.global.u32 %0, [%1];" : "=r"(v) : "l"(p) : "memory");
    return v;
}
__device__ __forceinline__ unsigned atom_add_acqrel_gpu(unsigned* p, unsigned v) {
    unsigned old;
    asm volatile("atom.acq_rel.gpu.global.add.u32 %0, [%1], %2;"
                 : "=r"(old) : "l"(p), "r"(v) : "memory");
    return old;
}
__device__ __forceinline__ void st_release_gpu(unsigned* p, unsigned v) {
    asm volatile("st.release.gpu.global.u32 [%0], %1;" :: "l"(p), "r"(v) : "memory");
}
__device__ __forceinline__ void st_relaxed_gpu(unsigned* p, unsigned v) {
    asm volatile("st.relaxed.gpu.global.u32 [%0], %1;" :: "l"(p), "r"(v) : "memory");
}

// ---------------- prologue: fp32 -> fp16, permuted for conflict-free LDS ----
// uint4 (r, it, lane) holds src k = it*256 + lane*4 + {0..3} in halves 0-3
// and src k = it*256 + 128 + lane*4 + {0..3} in halves 4-7.
__global__ void k_convert(const float* __restrict__ Wh) {
    size_t n = (size_t)R * R / 8;
    uint4* dst = (uint4*)d_Wh16;
    for (size_t o = (size_t)blockIdx.x * blockDim.x + threadIdx.x; o < n;
         o += (size_t)gridDim.x * blockDim.x) {
        size_t r = o >> 10;
        int rem = (int)(o & 1023);
        int it = rem >> 5, lane = rem & 31;
        const float* base = Wh + r * R + it * 256 + lane * 4;
        float4 a = *(const float4*)base;
        float4 b = *(const float4*)(base + 128);
        __half2 p0 = __floats2half2_rn(a.x, a.y);
        __half2 p1 = __floats2half2_rn(a.z, a.w);
        __half2 p2 = __floats2half2_rn(b.x, b.y);
        __half2 p3 = __floats2half2_rn(b.z, b.w);
        uint4 q;
        q.x = *reinterpret_cast<unsigned*>(&p0);
        q.y = *reinterpret_cast<unsigned*>(&p1);
        q.z = *reinterpret_cast<unsigned*>(&p2);
        q.w = *reinterpret_cast<unsigned*>(&p3);
        dst[o] = q;
    }
}

// ---------------- prologue ----------------
__global__ void k_prep(const float* __restrict__ Wout,
                       const float* __restrict__ xin,
                       float* __restrict__ out) {
    int tid = blockIdx.x * blockDim.x + threadIdx.x;
    int stride = gridDim.x * blockDim.x;
    for (int i = tid; i < R * D; i += stride) {
        int r = i / D, c = i % D;
        d_WoutT[i] = Wout[(size_t)c * R + r];
    }
    for (int i = tid; i < TTOT * D; i += stride) {
        float v = xin[i];
        out[TA_OFF + i] = v;
        if (i >= TW * D) out[TGT_OFF + i - TW * D] = v;
    }
    for (int i = tid; i < R; i += stride) { d_h[0][i] = 0.f; d_h[1][i] = 0.f; }
    if (tid < 3 * 8 * D) ((float*)d_osub)[tid] = 0.f;
    if (tid == 0) { d_bar_count = 0; d_bar_gen = 0; }
}

// ---------------- fence-free grid barrier (release/acquire, no MEMBAR.GPU) ----
__device__ __forceinline__ void gridbar() {
    __syncthreads();   // CTA-local happens-before: all warps' stores precede release
    if (threadIdx.x == 0) {
        unsigned g = ld_acquire_gpu(&d_bar_gen);       // read gen BEFORE arriving
        unsigned a = atom_add_acqrel_gpu(&d_bar_count, 1u);
        if (a == NB - 1) {
            st_relaxed_gpu(&d_bar_count, 0u);          // ordered before release below
            st_release_gpu(&d_bar_gen, g + 1);         // publishes ALL CTAs' writes
        } else {
            while (ld_acquire_gpu(&d_bar_gen) == g) { }
        }
    }
    __syncthreads();   // propagate acquire to all warps
}

__device__ __forceinline__ float dot8(uint4 q, float4 ha, float4 hb) {
    const __half2* h2 = reinterpret_cast<const __half2*>(&q);
    float2 f0 = __half22float2(h2[0]);
    float2 f1 = __half22float2(h2[1]);
    float2 f2 = __half22float2(h2[2]);
    float2 f3 = __half22float2(h2[3]);
    return f0.x * ha.x + f0.y * ha.y + f1.x * ha.z + f1.y * ha.w +
           f2.x * hb.x + f2.y * hb.y + f3.x * hb.z + f3.y * hb.w;
}

// dynamic smem layout (R11/R14/R16)
#define SM_WC    0                               // PINR*16384 = 180224 B
#define SM_H     (PINR * R * 2)                  // 8192 floats = 32768 B
#define SM_ORED  (SM_H + R * 4)                  // 16*64 floats = 4096 B
#define SM_X     (SM_ORED + WARPS * 64 * 4)      // 64 floats = 256 B
#define SM_TOTAL (SM_X + 64 * 4)                 // 217600 B

// 4-row / 3-row bodies; L0..L3 are uint4 expressions using `idx`
#define MM4(L0, L1, L2, L3, SERP)                                  \
    _Pragma("unroll 4")                                            \
    for (int it = 0; it < 32; ++it) {                              \
        int itt = (SERP) ? (31 - it) : it;                         \
        int kb = itt * 256 + lane * 4;                             \
        int idx = itt * 32 + lane;                                 \
        float4 ha = *(const float4*)(h_sh + kb);                   \
        float4 hb = *(const float4*)(h_sh + kb + 128);             \
        uint4 q0 = L0; uint4 q1 = L1; uint4 q2 = L2; uint4 q3 = L3;\
        acc0 += dot8(q0, ha, hb);                                  \
        acc1 += dot8(q1, ha, hb);                                  \
        acc2 += dot8(q2, ha, hb);                                  \
        acc3 += dot8(q3, ha, hb);                                  \
    }

#define MM3(L0, L1, L2, SERP)                                      \
    _Pragma("unroll 4")                                            \
    for (int it = 0; it < 32; ++it) {                              \
        int itt = (SERP) ? (31 - it) : it;                         \
        int kb = itt * 256 + lane * 4;                             \
        int idx = itt * 32 + lane;                                 \
        float4 ha = *(const float4*)(h_sh + kb);                   \
        float4 hb = *(const float4*)(h_sh + kb + 128);             \
        uint4 q0 = L0; uint4 q1 = L1; uint4 q2 = L2;               \
        acc0 += dot8(q0, ha, hb);                                  \
        acc1 += dot8(q1, ha, hb);                                  \
        acc2 += dot8(q2, ha, hb);                                  \
    }

// ---------------- persistent ESN kernel ----------------
__global__ void __launch_bounds__(NT, 1)
k_esn(const float* __restrict__ xin,
      const float* __restrict__ Win,
      float* __restrict__ out) {
    extern __shared__ char smem[];
    __half* wc   = (__half*)(smem + SM_WC);
    float*  h_sh = (float*)(smem + SM_H);
    float*  ored = (float*)(smem + SM_ORED);
    float*  x_sh = (float*)(smem + SM_X);

    const int tid  = threadIdx.x;
    const int lane = tid & 31;
    const int warp = tid >> 5;
    const int cta  = blockIdx.x;

    const unsigned long long POL_KEEP = mkpol_keep();

    // ---- uneven row partition (identical to R14/R16) ----
    const int nrows = (cta < 136) ? 54 : 53;
    const int rows0 = (cta < 136) ? 54 * cta : 7344 + 53 * (cta - 136);
    const int extra = nrows - 48;                       // # of 4-row warps (5 or 6)
    const int wr    = (warp < extra) ? 4 : 3;
    const int woff  = (warp < extra) ? 4 * warp : 4 * extra + 3 * (warp - extra);
    const int grow0 = rows0 + woff;

    // ---- pin row 0 of warps 0..10 in SMEM slot w ----
    {
        const unsigned long long POL_ONCE = mkpol_once();
        uint4* dst = (uint4*)wc;
        for (int i = tid; i < PINR * 1024; i += NT) {
            int slot = i >> 10;
            int off  = i & 1023;
            int wo = (slot < extra) ? 4 * slot : 4 * extra + 3 * (slot - extra);
            const uint4* src = (const uint4*)d_Wh16 + (size_t)(rows0 + wo) * 1024;
            dst[i] = ldg_pol(src + off, POL_ONCE);
        }
    }

    const uint4* g0 = (const uint4*)(d_Wh16 + (size_t)(grow0 + 0) * R);
    const uint4* g1 = (const uint4*)(d_Wh16 + (size_t)(grow0 + 1) * R);
    const uint4* g2 = (const uint4*)(d_Wh16 + (size_t)(grow0 + 2) * R);
    const uint4* g3 = (const uint4*)(d_Wh16 + (size_t)(grow0 + 3) * R);
    const uint4* c0 = (const uint4*)(wc + (size_t)warp * R);   // own pinned row 0
    const float* winr = Win + (size_t)grow0 * D + 2 * lane;
    const float* wt   = d_WoutT + (size_t)grow0 * D;
    __syncthreads();

    for (int s = 0; s < TTOT; ++s) {
        const bool rev = (s & 1);
        // ---- publish out(h_s), prepare x, recycle buffers ----
        if (tid < D) {
            float o = 0.f;
            if (cta == 0 || s >= TW) {
                #pragma unroll
                for (int b = 0; b < 8; ++b) o += __ldcg(&d_osub[s % 3][b][tid]);
            }
            if (cta == 0) {
                if (s >= 1 && s <= TW) out[PA_OFF + (s - 1) * D + tid] = o;
                if (s >= TW) {
                    out[PRED_OFF + (s - TW) * D + tid] = o;
                    out[PA_OFF + s * D + tid] = o;
                }
            }
            if (cta < 8) d_osub[(s + 2) % 3][cta][tid] = 0.f;
            x_sh[tid] = (s < TW) ? xin[(size_t)s * D + tid] : o;
        }
        // ---- stage h_s into shared (fp32, plain loads) ----
        {
            const float4* hsrc = (const float4*)d_h[s & 1];
            for (int i = tid; i < R / 4; i += NT) ((float4*)h_sh)[i] = hsrc[i];
        }
        __syncthreads();

        // ---- W_h @ h : row 0 pinned for warps 0-10; streamed rows serpentine, .cg ----
        float acc0 = 0.f, acc1 = 0.f, acc2 = 0.f, acc3 = 0.f;
        if (warp < PINR) {
            if (wr == 4) {
                MM4(c0[idx], ldg_pol(g1 + idx, POL_KEEP),
                    ldg_pol(g2 + idx, POL_KEEP), ldg_pol(g3 + idx, POL_KEEP), rev)
            } else {
                MM3(c0[idx], ldg_pol(g1 + idx, POL_KEEP),
                    ldg_pol(g2 + idx, POL_KEEP), rev)
            }
        } else {   // warps 11-15 always have wr == 3
            MM3(ldg_pol(g0 + idx, POL_KEEP), ldg_pol(g1 + idx, POL_KEEP),
                ldg_pol(g2 + idx, POL_KEEP), rev)
        }

        // ---- + W_in @ x ----
        {
            float xa = x_sh[2 * lane], xb = x_sh[2 * lane + 1];
            acc0 += winr[0]         * xa + winr[1]         * xb;
            acc1 += winr[D]         * xa + winr[D + 1]     * xb;
            acc2 += winr[2 * D]     * xa + winr[2 * D + 1] * xb;
            if (wr == 4)
                acc3 += winr[3 * D] * xa + winr[3 * D + 1] * xb;
        }
        #pragma unroll
        for (int o = 16; o; o >>= 1) {
            acc0 += __shfl_xor_sync(0xffffffffu, acc0, o);
            acc1 += __shfl_xor_sync(0xffffffffu, acc1, o);
            acc2 += __shfl_xor_sync(0xffffffffu, acc2, o);
            acc3 += __shfl_xor_sync(0xffffffffu, acc3, o);
        }
        // ---- lane-parallel tanh + h store + aug ----
        float pre = (lane == 0) ? acc0 : (lane == 1) ? acc1
                  : (lane == 2) ? acc2 : acc3;
        float hv = tanhf(pre);
        float av = 0.f;
        if (lane < wr) {
            d_h[(s + 1) & 1][grow0 + lane] = hv;
            av = (((grow0 + lane) & 1) == 0) ? hv * hv : hv;
        }
        float a0 = __shfl_sync(0xffffffffu, av, 0);
        float a1 = __shfl_sync(0xffffffffu, av, 1);
        float a2 = __shfl_sync(0xffffffffu, av, 2);
        float a3 = __shfl_sync(0xffffffffu, av, 3);

        // ---- fused readout partials: W_out @ aug(h_{s+1}) ----
        float p0 = wt[lane]      * a0 + wt[D + lane]      * a1 + wt[2 * D + lane]      * a2;
        float p1 = wt[32 + lane] * a0 + wt[D + 32 + lane] * a1 + wt[2 * D + 32 + lane] * a2;
        if (wr == 4) {
            p0 += wt[3 * D + lane]      * a3;
            p1 += wt[3 * D + 32 + lane] * a3;
        }
        ored[warp * 64 + lane]      = p0;
        ored[warp * 64 + 32 + lane] = p1;
        __syncthreads();
        if (tid < D) {
            float sum = 0.f;
            #pragma unroll
            for (int w = 0; w < WARPS; ++w) sum += ored[w * 64 + tid];
            atomicAdd(&d_osub[(s + 1) % 3][cta & 7][tid], sum);
        }
        gridbar();
    }
}

// ---------------- launch ----------------
extern "C" void kernel_launch(void* const* d_in, const int* in_sizes, int n_in,
                              void* d_out, int out_size) {
    const float* xin  = (const float*)d_in[0];
    const float* Win  = (const float*)d_in[1];
    const float* Whf  = (const float*)d_in[2];
    const float* Wout = (const float*)d_in[3];
    float* out = (float*)d_out;

    static bool attr_set = false;
    if (!attr_set) {
        cudaFuncSetAttribute(k_esn, cudaFuncAttributeMaxDynamicSharedMemorySize, SM_TOTAL);
        attr_set = true;
    }

    k_convert<<<4096, 256>>>(Whf);
    k_prep<<<1024, 256>>>(Wout, xin, out);
    k_esn<<<NB, NT, SM_TOTAL>>>(xin, Win, out);
}